// round 1
// baseline (speedup 1.0000x reference)
#include <cuda_runtime.h>

#define NBATCH   32768
#define WARPS    8
#define NTHREADS 256

// ---- shared memory float offsets ----
#define OFF_WMAP 0        // 49*24 = 1176
#define OFF_BMAP 1176     // 24
#define OFF_LNG  1200     // 32
#define OFF_LNB  1232     // 32
#define OFF_WQ   1264     // 4*72 = 288 (head stride padded 64->72, bank-conflict free)
#define OFF_WK   1552
#define OFF_WV   1840
#define OFF_WO   2128
#define OFF_BQ   2416
#define OFF_BK   2448
#define OFF_BV   2480
#define OFF_BO   2512
#define OFF_W1   2544     // 1024
#define OFF_B1   3568
#define OFF_W2   3600     // 1024
#define OFF_B2   4624
#define OFF_WC1  4656     // 2048
#define OFF_BC1  6704     // 64
#define OFF_WC2  6768     // 640
#define OFF_BC2  7408     // 10 (pad to 16)
#define WEIGHT_FLOATS 7424
#define SCRATCH_PER_WARP 1152
#define SMEM_FLOATS (WEIGHT_FLOATS + WARPS * SCRATCH_PER_WARP)
#define SMEM_BYTES  (SMEM_FLOATS * 4)

__device__ __forceinline__ float warp_ln(float v, float gg, float bb) {
    float s1 = v, s2 = v * v;
    #pragma unroll
    for (int o = 16; o; o >>= 1) {
        s1 += __shfl_xor_sync(0xffffffffu, s1, o);
        s2 += __shfl_xor_sync(0xffffffffu, s2, o);
    }
    float mu  = s1 * 0.03125f;
    float var = fmaf(s2, 0.03125f, -mu * mu);
    float rstd = rsqrtf(var + 1e-5f);
    return (v - mu) * rstd * gg + bb;
}

__global__ __launch_bounds__(NTHREADS, 3)
void vit_kernel(const float* __restrict__ img,
                const float* __restrict__ W_map, const float* __restrict__ b_map,
                const float* __restrict__ ln_g,  const float* __restrict__ ln_b,
                const float* __restrict__ Wq, const float* __restrict__ bq,
                const float* __restrict__ Wk, const float* __restrict__ bk,
                const float* __restrict__ Wv, const float* __restrict__ bv,
                const float* __restrict__ Wo, const float* __restrict__ bo,
                const float* __restrict__ W1, const float* __restrict__ b1,
                const float* __restrict__ W2, const float* __restrict__ b2,
                const float* __restrict__ Wc1, const float* __restrict__ bc1,
                const float* __restrict__ Wc2, const float* __restrict__ bc2,
                float* __restrict__ out)
{
    extern __shared__ float sm[];
    const int tid = threadIdx.x;

    // ---- cooperative weight staging ----
    for (int i = tid; i < 1176; i += NTHREADS) sm[OFF_WMAP + i] = W_map[i];
    for (int i = tid; i < 24;   i += NTHREADS) sm[OFF_BMAP + i] = b_map[i];
    for (int i = tid; i < 32;   i += NTHREADS) {
        sm[OFF_LNG + i] = ln_g[i]; sm[OFF_LNB + i] = ln_b[i];
        sm[OFF_BQ  + i] = bq[i];   sm[OFF_BK  + i] = bk[i];
        sm[OFF_BV  + i] = bv[i];   sm[OFF_BO  + i] = bo[i];
        sm[OFF_B1  + i] = b1[i];   sm[OFF_B2  + i] = b2[i];
    }
    for (int i = tid; i < 256; i += NTHREADS) {
        int h = i >> 6, r = i & 63;
        sm[OFF_WQ + h * 72 + r] = Wq[i];
        sm[OFF_WK + h * 72 + r] = Wk[i];
        sm[OFF_WV + h * 72 + r] = Wv[i];
        sm[OFF_WO + h * 72 + r] = Wo[i];
    }
    for (int i = tid; i < 1024; i += NTHREADS) { sm[OFF_W1 + i] = W1[i]; sm[OFF_W2 + i] = W2[i]; }
    for (int i = tid; i < 2048; i += NTHREADS) sm[OFF_WC1 + i] = Wc1[i];
    for (int i = tid; i < 64;   i += NTHREADS) sm[OFF_BC1 + i] = bc1[i];
    for (int i = tid; i < 640;  i += NTHREADS) sm[OFF_WC2 + i] = Wc2[i];
    for (int i = tid; i < 10;   i += NTHREADS) sm[OFF_BC2 + i] = bc2[i];
    __syncthreads();

    const int warp = tid >> 5, lane = tid & 31;
    const int imgIdx = blockIdx.x * WARPS + warp;     // grid is exact: 4096*8 = 32768
    float* sc = sm + WEIGHT_FLOATS + warp * SCRATCH_PER_WARP;
    const float* gim = img + imgIdx * 784;

    // ---- Phase A: load image, repack into patch-major layout [s][r*8+c] ----
    #pragma unroll
    for (int k = 0; k < 25; k++) {
        int i = lane + k * 32;
        if (i < 784) {
            float v = gim[i];
            int row = i / 28, col = i - row * 28;
            int pr = row / 7, rr = row - pr * 7;
            int pc = col / 7, cc = col - pc * 7;
            sc[(pr * 4 + pc) * 56 + rr * 8 + cc] = v;
        }
    }
    __syncwarp();

    // ---- Phase B: patch embedding -> x[s] (column = lane; lanes 0-7 are the zero pad) ----
    const int co  = lane - 8;
    const int co0 = co < 0 ? 0 : co;
    float x[16];
    {
        float bm = (co >= 0) ? sm[OFF_BMAP + co0] : 0.0f;
        #pragma unroll
        for (int s = 0; s < 16; s++) x[s] = bm;
    }
    #pragma unroll
    for (int r = 0; r < 7; r++) {
        float w[7];
        #pragma unroll
        for (int c = 0; c < 7; c++)
            w[c] = (co >= 0) ? sm[OFF_WMAP + (r * 7 + c) * 24 + co0] : 0.0f;
        #pragma unroll
        for (int s = 0; s < 16; s++) {
            float4 p0 = *reinterpret_cast<const float4*>(&sc[s * 56 + r * 8]);
            float4 p1 = *reinterpret_cast<const float4*>(&sc[s * 56 + r * 8 + 4]);
            float a = x[s];
            a = fmaf(p0.x, w[0], a); a = fmaf(p0.y, w[1], a);
            a = fmaf(p0.z, w[2], a); a = fmaf(p0.w, w[3], a);
            a = fmaf(p1.x, w[4], a); a = fmaf(p1.y, w[5], a);
            a = fmaf(p1.z, w[6], a);
            x[s] = a;
        }
    }

    // ---- Phase C: LayerNorm 1 (in place; keep x[0] residual) ----
    const float gg = sm[OFF_LNG + lane], bb = sm[OFF_LNB + lane];
    const float x0res = x[0];
    #pragma unroll
    for (int s = 0; s < 16; s++) x[s] = warp_ln(x[s], gg, bb);

    // write h to scratch [0:512] (patches dead)
    __syncwarp();
    #pragma unroll
    for (int s = 0; s < 16; s++) sc[s * 32 + lane] = x[s];
    __syncwarp();

    // ---- Phase D: k,v for all rows; q for row 0 only ----
    const int hh = lane >> 3, ee = lane & 7;
    const float* Wk_s = &sm[OFF_WK + hh * 72 + ee];
    const float* Wv_s = &sm[OFF_WV + hh * 72 + ee];
    const float* Wq_s = &sm[OFF_WQ + hh * 72 + ee];
    float kk[16], vv[16];
    {
        const float bk_r = sm[OFF_BK + lane], bv_r = sm[OFF_BV + lane];
        #pragma unroll
        for (int s = 0; s < 16; s++) {
            float4 h0 = *reinterpret_cast<const float4*>(&sc[s * 32 + hh * 8]);
            float4 h1 = *reinterpret_cast<const float4*>(&sc[s * 32 + hh * 8 + 4]);
            float ak = bk_r, av = bv_r;
            ak = fmaf(h0.x, Wk_s[0],  ak); av = fmaf(h0.x, Wv_s[0],  av);
            ak = fmaf(h0.y, Wk_s[8],  ak); av = fmaf(h0.y, Wv_s[8],  av);
            ak = fmaf(h0.z, Wk_s[16], ak); av = fmaf(h0.z, Wv_s[16], av);
            ak = fmaf(h0.w, Wk_s[24], ak); av = fmaf(h0.w, Wv_s[24], av);
            ak = fmaf(h1.x, Wk_s[32], ak); av = fmaf(h1.x, Wv_s[32], av);
            ak = fmaf(h1.y, Wk_s[40], ak); av = fmaf(h1.y, Wv_s[40], av);
            ak = fmaf(h1.z, Wk_s[48], ak); av = fmaf(h1.z, Wv_s[48], av);
            ak = fmaf(h1.w, Wk_s[56], ak); av = fmaf(h1.w, Wv_s[56], av);
            kk[s] = ak; vv[s] = av;
        }
    }
    float q0;
    {
        float4 h0 = *reinterpret_cast<const float4*>(&sc[hh * 8]);
        float4 h1 = *reinterpret_cast<const float4*>(&sc[hh * 8 + 4]);
        float a = sm[OFF_BQ + lane];
        a = fmaf(h0.x, Wq_s[0],  a); a = fmaf(h0.y, Wq_s[8],  a);
        a = fmaf(h0.z, Wq_s[16], a); a = fmaf(h0.w, Wq_s[24], a);
        a = fmaf(h1.x, Wq_s[32], a); a = fmaf(h1.y, Wq_s[40], a);
        a = fmaf(h1.z, Wq_s[48], a); a = fmaf(h1.w, Wq_s[56], a);
        q0 = a;
    }
    __syncwarp();   // everyone done reading h
    #pragma unroll
    for (int s = 0; s < 16; s++) { sc[s * 32 + lane] = kk[s]; sc[512 + s * 32 + lane] = vv[s]; }
    sc[1024 + lane] = q0;
    __syncwarp();

    // ---- Phase E: attention, row 0 (scores replicated within each 8-lane head group) ----
    float oe;
    {
        float4 qa = *reinterpret_cast<const float4*>(&sc[1024 + hh * 8]);
        float4 qb = *reinterpret_cast<const float4*>(&sc[1024 + hh * 8 + 4]);
        const float scale = 0.35355339059327373f;  // 1/sqrt(8)
        float scv[16];
        #pragma unroll
        for (int u = 0; u < 16; u++) {
            float4 k0 = *reinterpret_cast<const float4*>(&sc[u * 32 + hh * 8]);
            float4 k1 = *reinterpret_cast<const float4*>(&sc[u * 32 + hh * 8 + 4]);
            float t;
            t = qa.x * k0.x;          t = fmaf(qa.y, k0.y, t);
            t = fmaf(qa.z, k0.z, t);  t = fmaf(qa.w, k0.w, t);
            t = fmaf(qb.x, k1.x, t);  t = fmaf(qb.y, k1.y, t);
            t = fmaf(qb.z, k1.z, t);  t = fmaf(qb.w, k1.w, t);
            scv[u] = t * scale;
        }
        float m = scv[0];
        #pragma unroll
        for (int u = 1; u < 16; u++) m = fmaxf(m, scv[u]);
        float ssum = 0.0f;
        #pragma unroll
        for (int u = 0; u < 16; u++) { scv[u] = __expf(scv[u] - m); ssum += scv[u]; }
        float inv = __frcp_rn(ssum);
        float acc = 0.0f;
        #pragma unroll
        for (int u = 0; u < 16; u++) acc = fmaf(scv[u], sc[512 + u * 32 + lane], acc);
        oe = acc * inv;
    }
    __syncwarp();            // q row dead
    sc[1024 + lane] = oe;
    __syncwarp();

    // ---- output projection + residual -> mhsa row 0 ----
    float mh;
    {
        const float* Wo_s = &sm[OFF_WO + hh * 72 + ee];
        float4 o0 = *reinterpret_cast<const float4*>(&sc[1024 + hh * 8]);
        float4 o1 = *reinterpret_cast<const float4*>(&sc[1024 + hh * 8 + 4]);
        float a = sm[OFF_BO + lane];
        a = fmaf(o0.x, Wo_s[0],  a); a = fmaf(o0.y, Wo_s[8],  a);
        a = fmaf(o0.z, Wo_s[16], a); a = fmaf(o0.w, Wo_s[24], a);
        a = fmaf(o1.x, Wo_s[32], a); a = fmaf(o1.y, Wo_s[40], a);
        a = fmaf(o1.z, Wo_s[48], a); a = fmaf(o1.w, Wo_s[56], a);
        mh = a + x0res;
    }

    // ---- LayerNorm 2 (row 0 only) ----
    float h2 = warp_ln(mh, gg, bb);
    __syncwarp();
    sc[1024 + lane] = h2;
    __syncwarp();

    // ---- MLP row 0: y1 = relu(h2 @ W1 + b1) ----
    float y1;
    {
        float a = sm[OFF_B1 + lane];
        #pragma unroll
        for (int d4 = 0; d4 < 8; d4++) {
            float4 hv = *reinterpret_cast<const float4*>(&sc[1024 + d4 * 4]);
            a = fmaf(hv.x, sm[OFF_W1 + (d4 * 4 + 0) * 32 + lane], a);
            a = fmaf(hv.y, sm[OFF_W1 + (d4 * 4 + 1) * 32 + lane], a);
            a = fmaf(hv.z, sm[OFF_W1 + (d4 * 4 + 2) * 32 + lane], a);
            a = fmaf(hv.w, sm[OFF_W1 + (d4 * 4 + 3) * 32 + lane], a);
        }
        y1 = fmaxf(a, 0.0f);
    }
    __syncwarp();
    sc[1024 + lane] = y1;
    __syncwarp();

    // ---- y2 = y1 @ W2 + b2 ; enc0 = mhsa + y2 ----
    float enc0;
    {
        float a = sm[OFF_B2 + lane];
        #pragma unroll
        for (int d4 = 0; d4 < 8; d4++) {
            float4 hv = *reinterpret_cast<const float4*>(&sc[1024 + d4 * 4]);
            a = fmaf(hv.x, sm[OFF_W2 + (d4 * 4 + 0) * 32 + lane], a);
            a = fmaf(hv.y, sm[OFF_W2 + (d4 * 4 + 1) * 32 + lane], a);
            a = fmaf(hv.z, sm[OFF_W2 + (d4 * 4 + 2) * 32 + lane], a);
            a = fmaf(hv.w, sm[OFF_W2 + (d4 * 4 + 3) * 32 + lane], a);
        }
        enc0 = mh + a;
    }
    __syncwarp();
    sc[1024 + lane] = enc0;
    __syncwarp();

    // ---- classifier head: c1 = relu(enc0 @ Wc1 + bc1)  (64 outputs -> 2/lane) ----
    {
        float a0 = sm[OFF_BC1 + lane];
        float a1 = sm[OFF_BC1 + 32 + lane];
        #pragma unroll
        for (int d4 = 0; d4 < 8; d4++) {
            float4 ev = *reinterpret_cast<const float4*>(&sc[1024 + d4 * 4]);
            int b = OFF_WC1 + (d4 * 4) * 64 + lane;
            a0 = fmaf(ev.x, sm[b +   0], a0); a1 = fmaf(ev.x, sm[b +  32], a1);
            a0 = fmaf(ev.y, sm[b +  64], a0); a1 = fmaf(ev.y, sm[b +  96], a1);
            a0 = fmaf(ev.z, sm[b + 128], a0); a1 = fmaf(ev.z, sm[b + 160], a1);
            a0 = fmaf(ev.w, sm[b + 192], a0); a1 = fmaf(ev.w, sm[b + 224], a1);
        }
        a0 = fmaxf(a0, 0.0f); a1 = fmaxf(a1, 0.0f);
        __syncwarp();
        sc[1056 + lane] = a0;
        sc[1056 + 32 + lane] = a1;
        __syncwarp();
    }

    // ---- c2 = c1 @ Wc2 + bc2 -> 10 logits (lanes 0-9) ----
    if (lane < 10) {
        float a = sm[OFF_BC2 + lane];
        #pragma unroll
        for (int m4 = 0; m4 < 16; m4++) {
            float4 cv = *reinterpret_cast<const float4*>(&sc[1056 + m4 * 4]);
            a = fmaf(cv.x, sm[OFF_WC2 + (m4 * 4 + 0) * 10 + lane], a);
            a = fmaf(cv.y, sm[OFF_WC2 + (m4 * 4 + 1) * 10 + lane], a);
            a = fmaf(cv.z, sm[OFF_WC2 + (m4 * 4 + 2) * 10 + lane], a);
            a = fmaf(cv.w, sm[OFF_WC2 + (m4 * 4 + 3) * 10 + lane], a);
        }
        out[imgIdx * 10 + lane] = a;
    }
}

extern "C" void kernel_launch(void* const* d_in, const int* in_sizes, int n_in,
                              void* d_out, int out_size) {
    (void)in_sizes; (void)n_in; (void)out_size;
    const float* img   = (const float*)d_in[0];
    const float* W_map = (const float*)d_in[1];
    const float* b_map = (const float*)d_in[2];
    const float* ln_g  = (const float*)d_in[3];
    const float* ln_b  = (const float*)d_in[4];
    const float* Wq    = (const float*)d_in[5];
    const float* bq    = (const float*)d_in[6];
    const float* Wk    = (const float*)d_in[7];
    const float* bk    = (const float*)d_in[8];
    const float* Wv    = (const float*)d_in[9];
    const float* bv    = (const float*)d_in[10];
    const float* Wo    = (const float*)d_in[11];
    const float* bo    = (const float*)d_in[12];
    const float* W1    = (const float*)d_in[13];
    const float* b1    = (const float*)d_in[14];
    const float* W2    = (const float*)d_in[15];
    const float* b2    = (const float*)d_in[16];
    const float* Wc1   = (const float*)d_in[17];
    const float* bc1   = (const float*)d_in[18];
    const float* Wc2   = (const float*)d_in[19];
    const float* bc2   = (const float*)d_in[20];
    float* out = (float*)d_out;

    cudaFuncSetAttribute(vit_kernel, cudaFuncAttributeMaxDynamicSharedMemorySize, SMEM_BYTES);
    vit_kernel<<<NBATCH / WARPS, NTHREADS, SMEM_BYTES>>>(
        img, W_map, b_map, ln_g, ln_b, Wq, bq, Wk, bk, Wv, bv, Wo, bo,
        W1, b1, W2, b2, Wc1, bc1, Wc2, bc2, out);
}